// round 4
// baseline (speedup 1.0000x reference)
#include <cuda_runtime.h>
#include <cstdint>

// Problem constants: B=16384, F=16, V=300000, D=10
#define BSZ   16384
#define FDIM  16
#define VDIM  300000
#define DDIM  10
#define NPAIR 120                 // F*(F-1)/2
#define OUTW  1376                // 120*10 + 16*10 + 16
#define OUTW4 (OUTW / 4)          // 344

// Blackwell 256-bit global load (sm_100+): 8 floats in one LDG. Needs 32B alignment.
__device__ __forceinline__ void ldg_v8(const float* __restrict__ p, float* v) {
    asm("ld.global.nc.v8.f32 {%0,%1,%2,%3,%4,%5,%6,%7}, [%8];"
        : "=f"(v[0]), "=f"(v[1]), "=f"(v[2]), "=f"(v[3]),
          "=f"(v[4]), "=f"(v[5]), "=f"(v[6]), "=f"(v[7])
        : "l"(p));
}

__global__ __launch_bounds__(256, 8)
void feature_interact_kernel(const int*   __restrict__ x,    // [B, F]
                             const float* __restrict__ emb,  // [F, V, D]
                             const float* __restrict__ lin,  // [V, 1]
                             float*       __restrict__ out)  // [B, OUTW]
{
    __shared__ float E[FDIM * FDIM * DDIM];      // E[f][g][d] = emb[g, x[b,f]][d]
    __shared__ float lin_s[FDIM];
    __shared__ unsigned char pi_s[NPAIR], pj_s[NPAIR];

    const int b = blockIdx.x;
    const int t = threadIdx.x;

    // lin gather, once per block (hidden under the big gathers).
    if (t < FDIM) {
        lin_s[t] = __ldg(&lin[__ldg(&x[b * FDIM + t])]);
    }

    // triu(k=1) pair table.
    if (t < NPAIR) {
        int rem = t, i = 0;
        while (rem >= (FDIM - 1) - i) { rem -= (FDIM - 1) - i; ++i; }
        pi_s[t] = (unsigned char)i;
        pj_s[t] = (unsigned char)(i + 1 + rem);
    }

    // Gather phase: thread t owns (f = t>>4, g = t&15).
    // elt = (g*V + idx)*10 is even -> elt mod 8 in {0,2,4,6}.
    // Anchor at the 32B-aligned base and load a 64B window with two LDG.256
    // (branch-free, uniform per warp), then a 2-level constant-index select.
    // Window covers exactly the same 2 DRAM sectors as the 40B vector.
    // Max elt = (15*300000+299999)*10 = 47,999,990; (elt & ~7) + 16 <= 48,000,000. Safe.
    {
        const int f = t >> 4;
        const int g = t & (FDIM - 1);
        const int idx = __ldg(&x[b * FDIM + f]);
        const size_t elt = ((size_t)g * VDIM + (size_t)idx) * DDIM;
        const float* base = emb + (elt & ~(size_t)7);   // 32B-aligned
        const int off = (int)(elt & 7);                 // 0, 2, 4, or 6

        float W[16];
        ldg_v8(base, W);
        ldg_v8(base + 8, W + 8);

        // level 1: shift by 4 if (off & 4)
        float A[12];
        const bool s4 = (off & 4) != 0;
        #pragma unroll
        for (int k = 0; k < 12; ++k) A[k] = s4 ? W[k + 4] : W[k];
        // level 2: shift by 2 if (off & 2)
        const bool s2 = (off & 2) != 0;
        float2* dst = reinterpret_cast<float2*>(E + t * DDIM);  // 8B-aligned
        #pragma unroll
        for (int k = 0; k < 5; ++k) {
            float lo = s2 ? A[2 * k + 2] : A[2 * k];
            float hi = s2 ? A[2 * k + 3] : A[2 * k + 1];
            dst[k] = make_float2(lo, hi);
        }
    }
    __syncthreads();

    // Output phase: 344 float4 stores per row (row stride 5504B is 16B-aligned).
    float4* orow4 = reinterpret_cast<float4*>(out + (size_t)b * OUTW);
    for (int q = t; q < OUTW4; q += 256) {
        float r[4];
        #pragma unroll
        for (int e = 0; e < 4; ++e) {
            const int k = q * 4 + e;
            float vv;
            if (k < NPAIR * DDIM) {
                int p = k / DDIM, d = k - p * DDIM;
                int i = pi_s[p], j = pj_s[p];
                vv = E[(i * FDIM + j) * DDIM + d] * E[(j * FDIM + i) * DDIM + d];
            } else if (k < NPAIR * DDIM + FDIM * DDIM) {
                int k2 = k - NPAIR * DDIM;
                int f = k2 / DDIM, d = k2 - f * DDIM;
                vv = E[(f * FDIM + f) * DDIM + d];
            } else {
                vv = lin_s[k - (NPAIR * DDIM + FDIM * DDIM)];
            }
            r[e] = vv;
        }
        orow4[q] = make_float4(r[0], r[1], r[2], r[3]);
    }
}

extern "C" void kernel_launch(void* const* d_in, const int* in_sizes, int n_in,
                              void* d_out, int out_size)
{
    const int*   x   = nullptr;
    const float* emb = nullptr;
    const float* lin = nullptr;
    for (int i = 0; i < n_in; ++i) {
        if      (in_sizes[i] == BSZ * FDIM)          x   = (const int*)d_in[i];
        else if (in_sizes[i] == FDIM * VDIM * DDIM)  emb = (const float*)d_in[i];
        else if (in_sizes[i] == VDIM)                lin = (const float*)d_in[i];
    }
    feature_interact_kernel<<<BSZ, 256>>>(x, emb, lin, (float*)d_out);
}

// round 5
// speedup vs baseline: 1.0025x; 1.0025x over previous
#include <cuda_runtime.h>
#include <cstdint>

// Problem constants: B=16384, F=16, V=300000, D=10
#define BSZ   16384
#define FDIM  16
#define VDIM  300000
#define DDIM  10
#define NPAIR 120                 // F*(F-1)/2
#define OUTW  1376                // 120*10 + 16*10 + 16
#define OUTW4 (OUTW / 4)          // 344
#define SPB   2                   // samples per block

__global__ __launch_bounds__(256)
void feature_interact_kernel(const int*   __restrict__ x,    // [B, F]
                             const float* __restrict__ emb,  // [F, V, D]
                             const float* __restrict__ lin,  // [V, 1]
                             float*       __restrict__ out)  // [B, OUTW]
{
    __shared__ float E[SPB][FDIM * FDIM * DDIM];  // E[s][f][g][d] = emb[g, x[b+s,f]][d]
    __shared__ float lin_s[SPB][FDIM];
    __shared__ unsigned char pi_s[NPAIR], pj_s[NPAIR];

    const int b0 = blockIdx.x * SPB;
    const int t  = threadIdx.x;

    // lin gathers for both samples (32 threads), hidden under the big gathers.
    if (t < SPB * FDIM) {
        const int s = t >> 4, f = t & (FDIM - 1);
        lin_s[s][f] = __ldg(&lin[__ldg(&x[(b0 + s) * FDIM + f])]);
    }

    // triu(k=1) pair table.
    if (t < NPAIR) {
        int rem = t, i = 0;
        while (rem >= (FDIM - 1) - i) { rem -= (FDIM - 1) - i; ++i; }
        pi_s[t] = (unsigned char)i;
        pj_s[t] = (unsigned char)(i + 1 + rem);
    }

    // Gather phase: thread t owns (f = t>>4, g = t&15) for BOTH samples.
    // All index loads first, then all vector loads -> 6 loads in flight.
    {
        const int f = t >> 4;
        const int g = t & (FDIM - 1);

        const float* base[SPB];
        #pragma unroll
        for (int s = 0; s < SPB; ++s) {
            const int idx = __ldg(&x[(b0 + s) * FDIM + f]);
            base[s] = emb + ((size_t)g * VDIM + (size_t)idx) * DDIM;
        }

        float v[SPB][10];
        #pragma unroll
        for (int s = 0; s < SPB; ++s) {
            const float* bp = base[s];
            if ((((uintptr_t)bp) & 15) == 0) {
                float4 a = __ldg(reinterpret_cast<const float4*>(bp));
                float4 c = __ldg(reinterpret_cast<const float4*>(bp + 4));
                float2 e = __ldg(reinterpret_cast<const float2*>(bp + 8));
                v[s][0]=a.x; v[s][1]=a.y; v[s][2]=a.z; v[s][3]=a.w;
                v[s][4]=c.x; v[s][5]=c.y; v[s][6]=c.z; v[s][7]=c.w;
                v[s][8]=e.x; v[s][9]=e.y;
            } else {
                float2 a = __ldg(reinterpret_cast<const float2*>(bp));
                float4 c = __ldg(reinterpret_cast<const float4*>(bp + 2));
                float4 e = __ldg(reinterpret_cast<const float4*>(bp + 6));
                v[s][0]=a.x; v[s][1]=a.y;
                v[s][2]=c.x; v[s][3]=c.y; v[s][4]=c.z; v[s][5]=c.w;
                v[s][6]=e.x; v[s][7]=e.y; v[s][8]=e.z; v[s][9]=e.w;
            }
        }

        #pragma unroll
        for (int s = 0; s < SPB; ++s) {
            float2* dst = reinterpret_cast<float2*>(&E[s][t * DDIM]);  // 8B-aligned
            #pragma unroll
            for (int k = 0; k < 5; ++k)
                dst[k] = make_float2(v[s][2*k], v[s][2*k+1]);
        }
    }
    __syncthreads();

    // Output phase: 344 float4 stores per row, both rows.
    #pragma unroll
    for (int s = 0; s < SPB; ++s) {
        float4* orow4 = reinterpret_cast<float4*>(out + (size_t)(b0 + s) * OUTW);
        const float* Es = E[s];
        for (int q = t; q < OUTW4; q += 256) {
            float r[4];
            #pragma unroll
            for (int e = 0; e < 4; ++e) {
                const int k = q * 4 + e;
                float vv;
                if (k < NPAIR * DDIM) {
                    int p = k / DDIM, d = k - p * DDIM;
                    int i = pi_s[p], j = pj_s[p];
                    vv = Es[(i * FDIM + j) * DDIM + d] * Es[(j * FDIM + i) * DDIM + d];
                } else if (k < NPAIR * DDIM + FDIM * DDIM) {
                    int k2 = k - NPAIR * DDIM;
                    int f = k2 / DDIM, d = k2 - f * DDIM;
                    vv = Es[(f * FDIM + f) * DDIM + d];
                } else {
                    vv = lin_s[s][k - (NPAIR * DDIM + FDIM * DDIM)];
                }
                r[e] = vv;
            }
            orow4[q] = make_float4(r[0], r[1], r[2], r[3]);
        }
    }
}

extern "C" void kernel_launch(void* const* d_in, const int* in_sizes, int n_in,
                              void* d_out, int out_size)
{
    const int*   x   = nullptr;
    const float* emb = nullptr;
    const float* lin = nullptr;
    for (int i = 0; i < n_in; ++i) {
        if      (in_sizes[i] == BSZ * FDIM)          x   = (const int*)d_in[i];
        else if (in_sizes[i] == FDIM * VDIM * DDIM)  emb = (const float*)d_in[i];
        else if (in_sizes[i] == VDIM)                lin = (const float*)d_in[i];
    }
    feature_interact_kernel<<<BSZ / SPB, 256>>>(x, emb, lin, (float*)d_out);
}